// round 4
// baseline (speedup 1.0000x reference)
#include <cuda_runtime.h>
#include <cstdint>
#include <math.h>

#define DEVI __device__ __forceinline__

static constexpr int BDIM  = 4096;
static constexpr int INDIM = 1024;
static constexpr int HDIM  = 2048;
static constexpr int KDIM  = HDIM + INDIM;        // 3072
static constexpr int MT  = 128;                   // CTA M tile
static constexpr int NG  = 64;                    // CTA N tile per gate
static constexpr int NTT = 4 * NG;                // 256 total N rows in smem
static constexpr int KT  = 32;                    // K chunk (floats) = 128B row
static constexpr int NCHUNK = KDIM / KT;          // 96
static constexpr int STAGES = 3;
static constexpr int A_BYTES   = MT  * 128;       // 16384
static constexpr int B_BYTES   = NTT * 128;       // 32768
static constexpr int STG_BYTES = A_BYTES + B_BYTES;   // 49152
static constexpr int SMEM_TOTAL = STAGES * STG_BYTES; // 147456
static constexpr int NTHR = 512;

// tf32-rounded, k-permuted scratch (device globals: allocation-free)
__device__ __align__(1024) float g_A[(size_t)BDIM * KDIM];      // [B][K]  (hx concat)
__device__ __align__(1024) float g_W[(size_t)4 * HDIM * KDIM];  // [4][H][K]

// ---------------- helpers ----------------
DEVI uint32_t smem_u32(const void* p) {
    uint32_t a;
    asm("{ .reg .u64 t; cvta.to.shared.u64 t, %1; cvt.u32.u64 %0, t; }" : "=r"(a) : "l"(p));
    return a;
}
DEVI float to_tf32(float x) {
    uint32_t u;
    asm("cvt.rna.tf32.f32 %0, %1;" : "=r"(u) : "f"(x));
    return __uint_as_float(u);
}
DEVI void cp16(uint32_t dst, const float* src) {
    asm volatile("cp.async.cg.shared.global [%0], [%1], 16;" :: "r"(dst), "l"(src) : "memory");
}
DEVI void cp_commit() { asm volatile("cp.async.commit_group;" ::: "memory"); }
DEVI void cp_wait1()  { asm volatile("cp.async.wait_group 1;" ::: "memory"); }
DEVI void cp_wait0()  { asm volatile("cp.async.wait_group 0;" ::: "memory"); }

struct U2 { uint32_t x, y; };
DEVI U2 lds64u(uint32_t a, int imm) {
    U2 v;
    asm("ld.shared.v2.u32 {%0,%1}, [%2];" : "=r"(v.x), "=r"(v.y) : "r"(a + imm));
    return v;
}
DEVI void mma8(float* d, U2 alo, U2 ahi, U2 b) {
    asm("mma.sync.aligned.m16n8k8.row.col.f32.tf32.tf32.f32 "
        "{%0,%1,%2,%3}, {%4,%5,%6,%7}, {%8,%9}, {%0,%1,%2,%3};"
        : "+f"(d[0]), "+f"(d[1]), "+f"(d[2]), "+f"(d[3])
        : "r"(alo.x), "r"(ahi.x), "r"(alo.y), "r"(ahi.y),
          "r"(b.x),   "r"(b.y));
}
DEVI float sigmoidf_(float x) { return __fdividef(1.0f, 1.0f + __expf(-x)); }
DEVI float tanhf_(float x)    { return 2.0f * sigmoidf_(2.0f * x) - 1.0f; }

// ------------- merged prep: tf32-round + k-permute ([0,4,1,5,2,6,3,7] per k8) -------------
static constexpr int A_GRP = BDIM * (KDIM / 8);          // 1572864
static constexpr int W_GRP = 4 * HDIM * (KDIM / 8);      // 3145728
__global__ void prep_all(const float* __restrict__ x,  const float* __restrict__ ph,
                         const float* __restrict__ Wi, const float* __restrict__ Wf,
                         const float* __restrict__ Wo, const float* __restrict__ Wc) {
    const int total = A_GRP + W_GRP;
    for (int i = blockIdx.x * blockDim.x + threadIdx.x; i < total;
         i += gridDim.x * blockDim.x) {
        const float* src;
        float* dst;
        if (i < A_GRP) {
            int b  = i / (KDIM / 8);
            int k0 = (i - b * (KDIM / 8)) * 8;
            src = (k0 < HDIM) ? (ph + (size_t)b * HDIM + k0)
                              : (x  + (size_t)b * INDIM + (k0 - HDIM));
            dst = g_A + (size_t)b * KDIM + k0;
        } else {
            int j = i - A_GRP;
            const int per_gate = HDIM * (KDIM / 8);
            int g   = j / per_gate;
            int off = j - g * per_gate;
            const float* W = (g == 0) ? Wi : (g == 1) ? Wf : (g == 2) ? Wo : Wc;
            src = W + (size_t)off * 8;
            dst = g_W + (size_t)g * HDIM * KDIM + (size_t)off * 8;
        }
        float4 lo = ((const float4*)src)[0];
        float4 hi = ((const float4*)src)[1];
        ((float4*)dst)[0] = make_float4(to_tf32(lo.x), to_tf32(hi.x), to_tf32(lo.y), to_tf32(hi.y));
        ((float4*)dst)[1] = make_float4(to_tf32(lo.z), to_tf32(hi.z), to_tf32(lo.w), to_tf32(hi.w));
    }
}

// ---------------- main fused LSTM GEMM (mma.sync tf32, 512 thr) ----------------
__global__ __launch_bounds__(NTHR, 1)
void lstm_main(const float* __restrict__ prev_c, float* __restrict__ out) {
    extern __shared__ char smem[];
    const uint32_t sb = smem_u32(smem);
    const int tid  = threadIdx.x;
    const int lane = tid & 31;
    const int wid  = tid >> 5;
    const int warp_m = wid & 3;        // 4 warps over M (32 rows each)
    const int warp_n = wid >> 2;       // 4 warps over N (16 cols/gate each)
    const int q   = lane >> 2;         // 0..7
    const int cid = lane & 3;          // 0..3
    const int m0 = blockIdx.x * MT;
    const int n0 = blockIdx.y * NG;

    // ---- cp.async slot setup (6 x 16B per thread per stage) ----
    const float* a_src[2]; uint32_t a_dst[2];
#pragma unroll
    for (int it = 0; it < 2; it++) {
        int i = tid + NTHR * it;           // 0..1023
        int row = i >> 3, u = i & 7;
        a_src[it] = g_A + (size_t)(m0 + row) * KDIM + u * 4;
        a_dst[it] = sb + row * 128 + (((u ^ (row & 7))) << 4);
    }
    const float* b_src[4]; uint32_t b_dst[4];
#pragma unroll
    for (int it = 0; it < 4; it++) {
        int i = tid + NTHR * it;           // 0..2047
        int row = i >> 3, u = i & 7;       // row: gate*64 + n_local
        int gate = row >> 6, nl = row & 63;
        b_src[it] = g_W + ((size_t)gate * HDIM + (n0 + nl)) * KDIM + u * 4;
        b_dst[it] = sb + A_BYTES + row * 128 + (((u ^ (row & 7))) << 4);
    }

    // ---- fragment base addresses ----
    // For every fragment, row & 7 == q, so the swizzle term is warp-constant and
    // all per-fragment deltas are compile-time immediates:
    //   A: + mt*2048 + h*1024      B: + g*8192 + nt*1024
    const uint32_t swz = (uint32_t)((((cid >> 1) ^ q) << 4) + 8 * (cid & 1));
    const uint32_t A0 = sb + (uint32_t)((warp_m * 32 + q) * 128) + swz;
    const uint32_t B0 = sb + A_BYTES + (uint32_t)((warp_n * 16 + q) * 128) + swz;

    float acc[2][4][2][4];                 // [mt][gate][nt][e]
#pragma unroll
    for (int mt = 0; mt < 2; mt++)
#pragma unroll
        for (int g = 0; g < 4; g++)
#pragma unroll
            for (int nt = 0; nt < 2; nt++)
#pragma unroll
                for (int e = 0; e < 4; e++) acc[mt][g][nt][e] = 0.0f;

    auto load_stage = [&](int chunk, int s) {
        const uint32_t so = (uint32_t)(s * STG_BYTES);
        const int ko = chunk * KT;
#pragma unroll
        for (int it = 0; it < 2; it++) cp16(a_dst[it] + so, a_src[it] + ko);
#pragma unroll
        for (int it = 0; it < 4; it++) cp16(b_dst[it] + so, b_src[it] + ko);
        cp_commit();
    };

    // prologue: stages 0,1
    load_stage(0, 0);
    load_stage(1, 1);

    for (int c = 0; c < NCHUNK; c++) {
        if (c == NCHUNK - 1) cp_wait0(); else cp_wait1();
        __syncthreads();

        if (c + 2 < NCHUNK) load_stage(c + 2, (c + 2) % STAGES);

        const uint32_t so = (uint32_t)((c % STAGES) * STG_BYTES);
        const uint32_t ca = A0 + so;
        const uint32_t cb = B0 + so;

#pragma unroll
        for (int kk = 0; kk < 4; kk++) {
            const uint32_t kx = (uint32_t)(kk << 5);
            const uint32_t ax = ca ^ kx;
            const uint32_t bx = cb ^ kx;
            U2 af[2][2];
#pragma unroll
            for (int mt = 0; mt < 2; mt++) {
                af[mt][0] = lds64u(ax, mt * 2048);
                af[mt][1] = lds64u(ax, mt * 2048 + 1024);
            }
            U2 bf[4][2];
#pragma unroll
            for (int g = 0; g < 4; g++) {
                bf[g][0] = lds64u(bx, g * 8192);
                bf[g][1] = lds64u(bx, g * 8192 + 1024);
            }
#pragma unroll
            for (int g = 0; g < 4; g++)
#pragma unroll
                for (int nt = 0; nt < 2; nt++)
#pragma unroll
                    for (int mt = 0; mt < 2; mt++)
                        mma8(acc[mt][g][nt], af[mt][0], af[mt][1], bf[g][nt]);
        }
        // no trailing barrier: next iteration's post-wait barrier orders slot reuse
    }

    // -------- fused LSTM epilogue (register-wise across gates) --------
#pragma unroll
    for (int mt = 0; mt < 2; mt++)
#pragma unroll
        for (int h = 0; h < 2; h++) {
            const int b = m0 + warp_m * 32 + mt * 16 + q + 8 * h;
            const float* pc = prev_c + (size_t)b * HDIM;
            float* oh = out + (size_t)b * HDIM;
            float* oc = out + (size_t)(BDIM + b) * HDIM;
#pragma unroll
            for (int nt = 0; nt < 2; nt++) {
                const int n = n0 + warp_n * 16 + nt * 8 + 2 * cid;
                float2 pcv = *(const float2*)(pc + n);
                float hv[2], cv[2];
#pragma unroll
                for (int e = 0; e < 2; e++) {
                    const float gi = acc[mt][0][nt][2 * h + e];
                    const float gf = acc[mt][1][nt][2 * h + e];
                    const float go = acc[mt][2][nt][2 * h + e];
                    const float gc = acc[mt][3][nt][2 * h + e];
                    const float iv = sigmoidf_(gi);
                    const float fv = sigmoidf_(gf);
                    const float ov = sigmoidf_(go);
                    const float ct = tanhf_(gc);
                    const float pcx = (e == 0) ? pcv.x : pcv.y;
                    const float cc = fv * pcx + iv * ct;
                    cv[e] = cc;
                    hv[e] = ov * tanhf_(cc);
                }
                *(float2*)(oh + n) = make_float2(hv[0], hv[1]);
                *(float2*)(oc + n) = make_float2(cv[0], cv[1]);
            }
        }
}

// ---------------- host launch ----------------
extern "C" void kernel_launch(void* const* d_in, const int* in_sizes, int n_in,
                              void* d_out, int out_size) {
    const float* x      = (const float*)d_in[0];
    const float* prev_h = (const float*)d_in[1];
    const float* prev_c = (const float*)d_in[2];
    const float* Wi     = (const float*)d_in[3];
    const float* Wf     = (const float*)d_in[4];
    const float* Wo     = (const float*)d_in[5];
    const float* Wc     = (const float*)d_in[6];
    float* out = (float*)d_out;

    prep_all<<<4608, 256>>>(x, prev_h, Wi, Wf, Wo, Wc);

    static bool attr_set = false;
    if (!attr_set) {
        cudaFuncSetAttribute(lstm_main, cudaFuncAttributeMaxDynamicSharedMemorySize,
                             SMEM_TOTAL);
        attr_set = true;
    }
    dim3 grid(BDIM / MT, HDIM / NG);   // (32, 32); x-fast -> CTAs sharing weights co-resident
    lstm_main<<<grid, NTHR, SMEM_TOTAL>>>(prev_c, out);
    (void)in_sizes; (void)n_in; (void)out_size;
}

// round 5
// speedup vs baseline: 1.0638x; 1.0638x over previous
#include <cuda_runtime.h>
#include <cstdint>
#include <math.h>

#define DEVI __device__ __forceinline__

static constexpr int BDIM  = 4096;
static constexpr int INDIM = 1024;
static constexpr int HDIM  = 2048;
static constexpr int KDIM  = HDIM + INDIM;        // 3072
static constexpr int MT  = 128;                   // CTA M tile
static constexpr int NG  = 64;                    // CTA N tile per gate
static constexpr int NTT = 4 * NG;                // 256 total N rows in smem
static constexpr int KT  = 32;                    // K chunk (floats) = 128B row
static constexpr int NCHUNK = KDIM / KT;          // 96
static constexpr int STAGES = 3;
static constexpr int A_BYTES   = MT  * 128;       // 16384
static constexpr int B_BYTES   = NTT * 128;       // 32768
static constexpr int STG_BYTES = A_BYTES + B_BYTES;   // 49152
static constexpr int SMEM_TOTAL = STAGES * STG_BYTES; // 147456
static constexpr int NTHR = 512;

// tf32-rounded, k-permuted scratch (device globals: allocation-free)
__device__ __align__(1024) float g_A[(size_t)BDIM * KDIM];      // [B][K]  (hx concat)
__device__ __align__(1024) float g_W[(size_t)4 * HDIM * KDIM];  // [4][H][K]

// ---------------- helpers ----------------
DEVI uint32_t smem_u32(const void* p) {
    uint32_t a;
    asm("{ .reg .u64 t; cvta.to.shared.u64 t, %1; cvt.u32.u64 %0, t; }" : "=r"(a) : "l"(p));
    return a;
}
DEVI float to_tf32(float x) {
    uint32_t u;
    asm("cvt.rna.tf32.f32 %0, %1;" : "=r"(u) : "f"(x));
    return __uint_as_float(u);
}
DEVI void cp16(uint32_t dst, const float* src) {
    asm volatile("cp.async.cg.shared.global [%0], [%1], 16;" :: "r"(dst), "l"(src) : "memory");
}
DEVI void cp_commit() { asm volatile("cp.async.commit_group;" ::: "memory"); }
DEVI void cp_wait1()  { asm volatile("cp.async.wait_group 1;" ::: "memory"); }
DEVI void cp_wait0()  { asm volatile("cp.async.wait_group 0;" ::: "memory"); }

struct U2 { uint32_t x, y; };
template <int IMM>
DEVI U2 lds64i(uint32_t a) {
    U2 v;
    asm("ld.shared.v2.u32 {%0,%1}, [%2+%3];" : "=r"(v.x), "=r"(v.y) : "r"(a), "n"(IMM));
    return v;
}
DEVI void mma8(float* d, U2 alo, U2 ahi, U2 b) {
    asm("mma.sync.aligned.m16n8k8.row.col.f32.tf32.tf32.f32 "
        "{%0,%1,%2,%3}, {%4,%5,%6,%7}, {%8,%9}, {%0,%1,%2,%3};"
        : "+f"(d[0]), "+f"(d[1]), "+f"(d[2]), "+f"(d[3])
        : "r"(alo.x), "r"(ahi.x), "r"(alo.y), "r"(ahi.y),
          "r"(b.x),   "r"(b.y));
}
DEVI float sigmoidf_(float x) { return __fdividef(1.0f, 1.0f + __expf(-x)); }
DEVI float tanhf_(float x)    { return 2.0f * sigmoidf_(2.0f * x) - 1.0f; }

// ------------- merged prep: tf32-round + k-permute ([0,4,1,5,2,6,3,7] per k8) -------------
static constexpr int A_GRP = BDIM * (KDIM / 8);          // 1572864
static constexpr int W_GRP = 4 * HDIM * (KDIM / 8);      // 3145728
__global__ void prep_all(const float* __restrict__ x,  const float* __restrict__ ph,
                         const float* __restrict__ Wi, const float* __restrict__ Wf,
                         const float* __restrict__ Wo, const float* __restrict__ Wc) {
    const int total = A_GRP + W_GRP;
    for (int i = blockIdx.x * blockDim.x + threadIdx.x; i < total;
         i += gridDim.x * blockDim.x) {
        const float* src;
        float* dst;
        if (i < A_GRP) {
            int b  = i / (KDIM / 8);
            int k0 = (i - b * (KDIM / 8)) * 8;
            src = (k0 < HDIM) ? (ph + (size_t)b * HDIM + k0)
                              : (x  + (size_t)b * INDIM + (k0 - HDIM));
            dst = g_A + (size_t)b * KDIM + k0;
        } else {
            int j = i - A_GRP;
            const int per_gate = HDIM * (KDIM / 8);
            int g   = j / per_gate;
            int off = j - g * per_gate;
            const float* W = (g == 0) ? Wi : (g == 1) ? Wf : (g == 2) ? Wo : Wc;
            src = W + (size_t)off * 8;
            dst = g_W + (size_t)g * HDIM * KDIM + (size_t)off * 8;
        }
        float4 lo = ((const float4*)src)[0];
        float4 hi = ((const float4*)src)[1];
        ((float4*)dst)[0] = make_float4(to_tf32(lo.x), to_tf32(hi.x), to_tf32(lo.y), to_tf32(hi.y));
        ((float4*)dst)[1] = make_float4(to_tf32(lo.z), to_tf32(hi.z), to_tf32(lo.w), to_tf32(hi.w));
    }
}

// ---------------- main fused LSTM GEMM (mma.sync tf32, 512 thr, 2x8 warps) ----------------
__global__ __launch_bounds__(NTHR, 1)
void lstm_main(const float* __restrict__ prev_c, float* __restrict__ out) {
    extern __shared__ char smem[];
    const uint32_t sb = smem_u32(smem);
    const int tid  = threadIdx.x;
    const int lane = tid & 31;
    const int wid  = tid >> 5;
    const int warp_m = wid & 1;        // 2 warps over M (64 rows each, m_frags=4)
    const int warp_n = wid >> 1;       // 8 warps over N (8 cols/gate each, n_frags=4)
    const int q   = lane >> 2;         // 0..7
    const int cid = lane & 3;          // 0..3
    const int m0 = blockIdx.x * MT;
    const int n0 = blockIdx.y * NG;

    // ---- cp.async bases (all slots = base + compile-time stride) ----
    const int srow = tid >> 3;         // 0..63
    const int su   = tid & 7;
    const float* a_srcb = g_A + (size_t)(m0 + srow) * KDIM + su * 4;   // + it*64*KDIM
    const float* b_srcb = g_W + (size_t)(n0 + srow) * KDIM + su * 4;   // + it*HDIM*KDIM
    const uint32_t sw_cp = (uint32_t)((su ^ (srow & 7)) << 4);
    const uint32_t a_dstb = sb + (uint32_t)(srow * 128) + sw_cp;            // + it*8192
    const uint32_t b_dstb = sb + A_BYTES + (uint32_t)(srow * 128) + sw_cp;  // + it*8192

    // ---- fragment base addresses (row&7 == q for all frags -> warp-constant swizzle) ----
    const uint32_t swz = (uint32_t)((((cid >> 1) ^ q) << 4) + 8 * (cid & 1));
    const uint32_t A0 = sb + (uint32_t)((warp_m * 64 + q) * 128) + swz;       // + mt*2048 + h*1024
    const uint32_t B0 = sb + A_BYTES + (uint32_t)((warp_n * 8 + q) * 128) + swz; // + g*8192

    float acc[4][4][4];                // [gate][mt][e]
#pragma unroll
    for (int g = 0; g < 4; g++)
#pragma unroll
        for (int mt = 0; mt < 4; mt++)
#pragma unroll
            for (int e = 0; e < 4; e++) acc[g][mt][e] = 0.0f;

    auto load_stage = [&](int chunk, int s) {
        const uint32_t so = (uint32_t)(s * STG_BYTES);
        const int ko = chunk * KT;
        cp16(a_dstb + so,        a_srcb + ko);
        cp16(a_dstb + so + 8192, a_srcb + ko + (size_t)64 * KDIM);
#pragma unroll
        for (int it = 0; it < 4; it++)
            cp16(b_dstb + so + it * 8192, b_srcb + ko + (size_t)it * HDIM * KDIM);
        cp_commit();
    };

    // prologue: stages 0,1
    load_stage(0, 0);
    load_stage(1, 1);

    U2 af[2][4][2];   // [buf][mt][h]
    U2 bf[2][4];      // [buf][gate]

    for (int c = 0; c < NCHUNK; c++) {
        if (c == NCHUNK - 1) cp_wait0(); else cp_wait1();
        __syncthreads();

        if (c + 2 < NCHUNK) load_stage(c + 2, (c + 2) % STAGES);

        const uint32_t so = (uint32_t)((c % STAGES) * STG_BYTES);
        const uint32_t ca = A0 + so;
        const uint32_t cb = B0 + so;

        // prime kk=0
#pragma unroll
        for (int mt = 0; mt < 4; mt++) {
            af[0][mt][0] = (mt == 0) ? lds64i<0>(ca) : (mt == 1) ? lds64i<2048>(ca)
                         : (mt == 2) ? lds64i<4096>(ca) : lds64i<6144>(ca);
            af[0][mt][1] = (mt == 0) ? lds64i<1024>(ca) : (mt == 1) ? lds64i<3072>(ca)
                         : (mt == 2) ? lds64i<5120>(ca) : lds64i<7168>(ca);
        }
        bf[0][0] = lds64i<0>(cb);     bf[0][1] = lds64i<8192>(cb);
        bf[0][2] = lds64i<16384>(cb); bf[0][3] = lds64i<24576>(cb);

#pragma unroll
        for (int kk = 0; kk < 4; kk++) {
            const int cur = kk & 1, nxt = cur ^ 1;
            if (kk < 3) {
                const uint32_t kx = (uint32_t)((kk + 1) << 5);
                const uint32_t ax = ca ^ kx;
                const uint32_t bx = cb ^ kx;
                af[nxt][0][0] = lds64i<0>(ax);    af[nxt][0][1] = lds64i<1024>(ax);
                af[nxt][1][0] = lds64i<2048>(ax); af[nxt][1][1] = lds64i<3072>(ax);
                af[nxt][2][0] = lds64i<4096>(ax); af[nxt][2][1] = lds64i<5120>(ax);
                af[nxt][3][0] = lds64i<6144>(ax); af[nxt][3][1] = lds64i<7168>(ax);
                bf[nxt][0] = lds64i<0>(bx);     bf[nxt][1] = lds64i<8192>(bx);
                bf[nxt][2] = lds64i<16384>(bx); bf[nxt][3] = lds64i<24576>(bx);
            }
#pragma unroll
            for (int g = 0; g < 4; g++)
#pragma unroll
                for (int mt = 0; mt < 4; mt++)
                    mma8(acc[g][mt], af[cur][mt][0], af[cur][mt][1], bf[cur][g]);
        }
        // no trailing barrier: next iteration's post-wait barrier orders slot reuse
    }

    // -------- fused LSTM epilogue (register-wise across gates) --------
    const int n = n0 + warp_n * 8 + 2 * cid;
#pragma unroll
    for (int mt = 0; mt < 4; mt++)
#pragma unroll
        for (int h = 0; h < 2; h++) {
            const int b = m0 + warp_m * 64 + mt * 16 + q + 8 * h;
            const float* pc = prev_c + (size_t)b * HDIM;
            float* oh = out + (size_t)b * HDIM;
            float* oc = out + (size_t)(BDIM + b) * HDIM;
            float2 pcv = *(const float2*)(pc + n);
            float hv[2], cv[2];
#pragma unroll
            for (int e = 0; e < 2; e++) {
                const float gi = acc[0][mt][2 * h + e];
                const float gf = acc[1][mt][2 * h + e];
                const float go = acc[2][mt][2 * h + e];
                const float gc = acc[3][mt][2 * h + e];
                const float iv = sigmoidf_(gi);
                const float fv = sigmoidf_(gf);
                const float ov = sigmoidf_(go);
                const float ct = tanhf_(gc);
                const float pcx = (e == 0) ? pcv.x : pcv.y;
                const float cc = fv * pcx + iv * ct;
                cv[e] = cc;
                hv[e] = ov * tanhf_(cc);
            }
            *(float2*)(oh + n) = make_float2(hv[0], hv[1]);
            *(float2*)(oc + n) = make_float2(cv[0], cv[1]);
        }
}

// ---------------- host launch ----------------
extern "C" void kernel_launch(void* const* d_in, const int* in_sizes, int n_in,
                              void* d_out, int out_size) {
    const float* x      = (const float*)d_in[0];
    const float* prev_h = (const float*)d_in[1];
    const float* prev_c = (const float*)d_in[2];
    const float* Wi     = (const float*)d_in[3];
    const float* Wf     = (const float*)d_in[4];
    const float* Wo     = (const float*)d_in[5];
    const float* Wc     = (const float*)d_in[6];
    float* out = (float*)d_out;

    prep_all<<<4608, 256>>>(x, prev_h, Wi, Wf, Wo, Wc);

    static bool attr_set = false;
    if (!attr_set) {
        cudaFuncSetAttribute(lstm_main, cudaFuncAttributeMaxDynamicSharedMemorySize,
                             SMEM_TOTAL);
        attr_set = true;
    }
    dim3 grid(BDIM / MT, HDIM / NG);   // (32, 32); x-fast -> CTAs sharing weights co-resident
    lstm_main<<<grid, NTHR, SMEM_TOTAL>>>(prev_c, out);
    (void)in_sizes; (void)n_in; (void)out_size;
}

// round 6
// speedup vs baseline: 1.1035x; 1.0373x over previous
#include <cuda_runtime.h>
#include <cstdint>
#include <math.h>

#define DEVI __device__ __forceinline__

static constexpr int BDIM  = 4096;
static constexpr int INDIM = 1024;
static constexpr int HDIM  = 2048;
static constexpr int KDIM  = HDIM + INDIM;        // 3072
static constexpr int MT  = 128;                   // CTA M tile
static constexpr int NG  = 64;                    // CTA N tile per gate
static constexpr int NTT = 4 * NG;                // 256 total N rows in smem
static constexpr int KT  = 32;                    // K chunk (floats) = 128B row
static constexpr int NCHUNK = KDIM / KT;          // 96
static constexpr int STAGES = 3;
static constexpr int A_BYTES   = MT  * 128;       // 16384
static constexpr int B_BYTES   = NTT * 128;       // 32768
static constexpr int STG_BYTES = A_BYTES + B_BYTES;   // 49152
static constexpr int SMEM_TOTAL = STAGES * STG_BYTES; // 147456
static constexpr int NTHR = 256;

// tf32-rounded, k-permuted scratch (device globals: allocation-free)
__device__ __align__(1024) float g_A[(size_t)BDIM * KDIM];      // [B][K]  (hx concat)
__device__ __align__(1024) float g_W[(size_t)4 * HDIM * KDIM];  // [4][H][K]

// ---------------- helpers ----------------
DEVI uint32_t smem_u32(const void* p) {
    uint32_t a;
    asm("{ .reg .u64 t; cvta.to.shared.u64 t, %1; cvt.u32.u64 %0, t; }" : "=r"(a) : "l"(p));
    return a;
}
DEVI float to_tf32(float x) {
    uint32_t u;
    asm("cvt.rna.tf32.f32 %0, %1;" : "=r"(u) : "f"(x));
    return __uint_as_float(u);
}
DEVI void cp16(uint32_t dst, const float* src) {
    asm volatile("cp.async.cg.shared.global [%0], [%1], 16;" :: "r"(dst), "l"(src) : "memory");
}
DEVI void cp_commit() { asm volatile("cp.async.commit_group;" ::: "memory"); }
DEVI void cp_wait1()  { asm volatile("cp.async.wait_group 1;" ::: "memory"); }
DEVI void cp_wait0()  { asm volatile("cp.async.wait_group 0;" ::: "memory"); }

struct U2 { uint32_t x, y; };
template <int IMM>
DEVI U2 lds64i(uint32_t a) {
    U2 v;
    asm("ld.shared.v2.u32 {%0,%1}, [%2+%3];" : "=r"(v.x), "=r"(v.y) : "r"(a), "n"(IMM));
    return v;
}
DEVI void mma8(float* d, U2 alo, U2 ahi, U2 b) {
    asm("mma.sync.aligned.m16n8k8.row.col.f32.tf32.tf32.f32 "
        "{%0,%1,%2,%3}, {%4,%5,%6,%7}, {%8,%9}, {%0,%1,%2,%3};"
        : "+f"(d[0]), "+f"(d[1]), "+f"(d[2]), "+f"(d[3])
        : "r"(alo.x), "r"(ahi.x), "r"(alo.y), "r"(ahi.y),
          "r"(b.x),   "r"(b.y));
}
DEVI float sigmoidf_(float x) { return __fdividef(1.0f, 1.0f + __expf(-x)); }
DEVI float tanhf_(float x)    { return 2.0f * sigmoidf_(2.0f * x) - 1.0f; }

// ------------- merged prep: tf32-round + k-permute ([0,4,1,5,2,6,3,7] per k8) -------------
static constexpr int A_GRP = BDIM * (KDIM / 8);          // 1572864
static constexpr int W_GRP = 4 * HDIM * (KDIM / 8);      // 3145728
__global__ void prep_all(const float* __restrict__ x,  const float* __restrict__ ph,
                         const float* __restrict__ Wi, const float* __restrict__ Wf,
                         const float* __restrict__ Wo, const float* __restrict__ Wc) {
    const int total = A_GRP + W_GRP;
    for (int i = blockIdx.x * blockDim.x + threadIdx.x; i < total;
         i += gridDim.x * blockDim.x) {
        const float* src;
        float* dst;
        if (i < A_GRP) {
            int b  = i / (KDIM / 8);
            int k0 = (i - b * (KDIM / 8)) * 8;
            src = (k0 < HDIM) ? (ph + (size_t)b * HDIM + k0)
                              : (x  + (size_t)b * INDIM + (k0 - HDIM));
            dst = g_A + (size_t)b * KDIM + k0;
        } else {
            int j = i - A_GRP;
            const int per_gate = HDIM * (KDIM / 8);
            int g   = j / per_gate;
            int off = j - g * per_gate;
            const float* W = (g == 0) ? Wi : (g == 1) ? Wf : (g == 2) ? Wo : Wc;
            src = W + (size_t)off * 8;
            dst = g_W + (size_t)g * HDIM * KDIM + (size_t)off * 8;
        }
        float4 lo = ((const float4*)src)[0];
        float4 hi = ((const float4*)src)[1];
        ((float4*)dst)[0] = make_float4(to_tf32(lo.x), to_tf32(hi.x), to_tf32(lo.y), to_tf32(hi.y));
        ((float4*)dst)[1] = make_float4(to_tf32(lo.z), to_tf32(hi.z), to_tf32(lo.w), to_tf32(hi.w));
    }
}

// ------------- main fused LSTM GEMM (mma.sync tf32, 256 thr, 2x4 warps, fat tile) -------------
__global__ __launch_bounds__(NTHR, 1)
void lstm_main(const float* __restrict__ prev_c, float* __restrict__ out) {
    extern __shared__ char smem[];
    const uint32_t sb = smem_u32(smem);
    const int tid  = threadIdx.x;
    const int lane = tid & 31;
    const int wid  = tid >> 5;
    const int warp_m = wid & 1;        // 2 warps over M (64 rows each, m_frags=4)
    const int warp_n = wid >> 1;       // 4 warps over N (16 cols/gate, n_frags=2/gate)
    const int q   = lane >> 2;         // 0..7
    const int cid = lane & 3;          // 0..3
    const int m0 = blockIdx.x * MT;
    const int n0 = blockIdx.y * NG;

    // ---- cp.async bases (12 slots/thread/stage = base + compile-time stride) ----
    const int srow = tid >> 3;         // 0..31
    const int su   = tid & 7;
    const float* a_srcb = g_A + (size_t)(m0 + srow) * KDIM + su * 4;   // + it*32*KDIM
    const float* b_srcb = g_W + (size_t)(n0 + srow) * KDIM + su * 4;   // + ((it>>1)*HDIM+(it&1)*32)*KDIM
    const uint32_t sw_cp = (uint32_t)((su ^ (srow & 7)) << 4);
    const uint32_t a_dstb = sb + (uint32_t)(srow * 128) + sw_cp;            // + it*4096
    const uint32_t b_dstb = sb + A_BYTES + (uint32_t)(srow * 128) + sw_cp;  // + it*4096

    // ---- fragment bases (row&7 == q for all frags -> warp-constant swizzle) ----
    const uint32_t swz = (uint32_t)((((cid >> 1) ^ q) << 4) + 8 * (cid & 1));
    const uint32_t A0 = sb + (uint32_t)((warp_m * 64 + q) * 128) + swz;          // + mt*2048 + h*1024
    const uint32_t B0 = sb + A_BYTES + (uint32_t)((warp_n * 16 + q) * 128) + swz; // + g*8192 + nt*1024

    float acc[4][4][2][4];             // [gate][mt][nt][e]
#pragma unroll
    for (int g = 0; g < 4; g++)
#pragma unroll
        for (int mt = 0; mt < 4; mt++)
#pragma unroll
            for (int nt = 0; nt < 2; nt++)
#pragma unroll
                for (int e = 0; e < 4; e++) acc[g][mt][nt][e] = 0.0f;

    auto load_stage = [&](int chunk, int s) {
        const uint32_t so = (uint32_t)(s * STG_BYTES);
        const int ko = chunk * KT;
#pragma unroll
        for (int it = 0; it < 4; it++)
            cp16(a_dstb + so + it * 4096, a_srcb + ko + (size_t)it * 32 * KDIM);
#pragma unroll
        for (int it = 0; it < 8; it++)
            cp16(b_dstb + so + it * 4096,
                 b_srcb + ko + ((size_t)(it >> 1) * HDIM + (size_t)(it & 1) * 32) * KDIM);
        cp_commit();
    };

    // prologue: stages 0,1
    load_stage(0, 0);
    load_stage(1, 1);

    U2 af[2][4][2];   // [buf][mt][h]
    U2 bf[2][4][2];   // [buf][gate][nt]

    for (int c = 0; c < NCHUNK; c++) {
        if (c == NCHUNK - 1) cp_wait0(); else cp_wait1();
        __syncthreads();

        if (c + 2 < NCHUNK) load_stage(c + 2, (c + 2) % STAGES);

        const uint32_t so = (uint32_t)((c % STAGES) * STG_BYTES);
        const uint32_t ca = A0 + so;
        const uint32_t cb = B0 + so;

        // prime kk=0
        af[0][0][0] = lds64i<0>(ca);    af[0][0][1] = lds64i<1024>(ca);
        af[0][1][0] = lds64i<2048>(ca); af[0][1][1] = lds64i<3072>(ca);
        af[0][2][0] = lds64i<4096>(ca); af[0][2][1] = lds64i<5120>(ca);
        af[0][3][0] = lds64i<6144>(ca); af[0][3][1] = lds64i<7168>(ca);
        bf[0][0][0] = lds64i<0>(cb);     bf[0][0][1] = lds64i<1024>(cb);
        bf[0][1][0] = lds64i<8192>(cb);  bf[0][1][1] = lds64i<9216>(cb);
        bf[0][2][0] = lds64i<16384>(cb); bf[0][2][1] = lds64i<17408>(cb);
        bf[0][3][0] = lds64i<24576>(cb); bf[0][3][1] = lds64i<25600>(cb);

#pragma unroll
        for (int kk = 0; kk < 4; kk++) {
            const int cur = kk & 1, nxt = cur ^ 1;
            if (kk < 3) {
                const uint32_t kx = (uint32_t)((kk + 1) << 5);
                const uint32_t ax = ca ^ kx;
                const uint32_t bx = cb ^ kx;
                af[nxt][0][0] = lds64i<0>(ax);    af[nxt][0][1] = lds64i<1024>(ax);
                af[nxt][1][0] = lds64i<2048>(ax); af[nxt][1][1] = lds64i<3072>(ax);
                af[nxt][2][0] = lds64i<4096>(ax); af[nxt][2][1] = lds64i<5120>(ax);
                af[nxt][3][0] = lds64i<6144>(ax); af[nxt][3][1] = lds64i<7168>(ax);
                bf[nxt][0][0] = lds64i<0>(bx);     bf[nxt][0][1] = lds64i<1024>(bx);
                bf[nxt][1][0] = lds64i<8192>(bx);  bf[nxt][1][1] = lds64i<9216>(bx);
                bf[nxt][2][0] = lds64i<16384>(bx); bf[nxt][2][1] = lds64i<17408>(bx);
                bf[nxt][3][0] = lds64i<24576>(bx); bf[nxt][3][1] = lds64i<25600>(bx);
            }
#pragma unroll
            for (int g = 0; g < 4; g++)
#pragma unroll
                for (int nt = 0; nt < 2; nt++)
#pragma unroll
                    for (int mt = 0; mt < 4; mt++)
                        mma8(acc[g][mt][nt], af[cur][mt][0], af[cur][mt][1], bf[cur][g][nt]);
        }
        // no trailing barrier: next iteration's post-wait barrier orders slot reuse
    }

    // -------- fused LSTM epilogue (register-wise across gates) --------
#pragma unroll
    for (int mt = 0; mt < 4; mt++)
#pragma unroll
        for (int h = 0; h < 2; h++) {
            const int b = m0 + warp_m * 64 + mt * 16 + q + 8 * h;
            const float* pc = prev_c + (size_t)b * HDIM;
            float* oh = out + (size_t)b * HDIM;
            float* oc = out + (size_t)(BDIM + b) * HDIM;
#pragma unroll
            for (int nt = 0; nt < 2; nt++) {
                const int n = n0 + warp_n * 16 + nt * 8 + 2 * cid;
                float2 pcv = *(const float2*)(pc + n);
                float hv[2], cv[2];
#pragma unroll
                for (int e = 0; e < 2; e++) {
                    const float gi = acc[0][mt][nt][2 * h + e];
                    const float gf = acc[1][mt][nt][2 * h + e];
                    const float go = acc[2][mt][nt][2 * h + e];
                    const float gc = acc[3][mt][nt][2 * h + e];
                    const float iv = sigmoidf_(gi);
                    const float fv = sigmoidf_(gf);
                    const float ov = sigmoidf_(go);
                    const float ct = tanhf_(gc);
                    const float pcx = (e == 0) ? pcv.x : pcv.y;
                    const float cc = fv * pcx + iv * ct;
                    cv[e] = cc;
                    hv[e] = ov * tanhf_(cc);
                }
                *(float2*)(oh + n) = make_float2(hv[0], hv[1]);
                *(float2*)(oc + n) = make_float2(cv[0], cv[1]);
            }
        }
}

// ---------------- host launch ----------------
extern "C" void kernel_launch(void* const* d_in, const int* in_sizes, int n_in,
                              void* d_out, int out_size) {
    const float* x      = (const float*)d_in[0];
    const float* prev_h = (const float*)d_in[1];
    const float* prev_c = (const float*)d_in[2];
    const float* Wi     = (const float*)d_in[3];
    const float* Wf     = (const float*)d_in[4];
    const float* Wo     = (const float*)d_in[5];
    const float* Wc     = (const float*)d_in[6];
    float* out = (float*)d_out;

    prep_all<<<4608, 256>>>(x, prev_h, Wi, Wf, Wo, Wc);

    static bool attr_set = false;
    if (!attr_set) {
        cudaFuncSetAttribute(lstm_main, cudaFuncAttributeMaxDynamicSharedMemorySize,
                             SMEM_TOTAL);
        attr_set = true;
    }
    dim3 grid(BDIM / MT, HDIM / NG);   // (32, 32); x-fast -> CTAs sharing weights co-resident
    lstm_main<<<grid, NTHR, SMEM_TOTAL>>>(prev_c, out);
    (void)in_sizes; (void)n_in; (void)out_size;
}